// round 17
// baseline (speedup 1.0000x reference)
#include <cuda_runtime.h>
#include <cuda_bf16.h>
#include <math.h>

// Problem constants: x [16, 256, 128, 128] fp32, w [1, 2, 7, 7] fp32
// out [16, 1, 128, 128] fp32
#define B_  16
#define C_  256
#define H_  128
#define W_  128
#define HW_ (H_ * W_)          // 16384
#define HW4_ (HW_ / 4)         // 4096 float4 groups per plane
#define NCHUNK 2
#define CPC (C_ / NCHUNK)      // 128 channels per chunk
#define CPT (CPC / 2)          // 64 channels per thread (half-lane)

// Fused-kernel tiling: 8 rows x 32 cols per block -> 1024 blocks.
#define HT  8                  // output rows per tile
#define TRR (HT + 6)           // input rows incl. vertical halo = 14
#define GT  10                 // float4 groups incl. horizontal halo (8 + 2)
#define NIT (2 * TRR * GT)     // 280 combine items per block

typedef unsigned long long u64_t;

// Scratch: per-chunk partials [chunk][B][2][HW] (sum plane, max plane) = 4 MB
__device__ float g_part[NCHUNK * B_ * 2 * HW_];

// L2 evict-last store via cache-hint policy.
__device__ __forceinline__ void st_evict_last(float4* p, float4 v, u64_t pol) {
    asm volatile("st.global.L2::cache_hint.v4.f32 [%0], {%1, %2, %3, %4}, %5;"
                 :: "l"(p), "f"(v.x), "f"(v.y), "f"(v.z), "f"(v.w), "l"(pol)
                 : "memory");
}
__device__ __forceinline__ u64_t mk_evict_last_policy() {
    u64_t pol;
    asm volatile("createpolicy.fractional.L2::evict_last.b64 %0, 1.0;" : "=l"(pol));
    return pol;
}

// ---------------------------------------------------------------------------
// Kernel 1: partial sum+max over a 128-channel chunk, 1024 blocks (proven
// geometry). Block = (batch, chunk, 128-group span); 256 threads = 2 half-
// lanes x 128 groups; each thread runs the same 64-iter __ldcs loop as the
// 82.5%-DRAM R5 config; halves pair-combined through 4 KB smem.
// ---------------------------------------------------------------------------
__global__ __launch_bounds__(256) void reduce_partial_kernel(const float* __restrict__ x) {
    __shared__ float4 s_sum[128];
    __shared__ float4 s_max[128];

    int b     = blockIdx.x >> 6;            // 64 blocks per batch
    int chunk = (blockIdx.x >> 5) & 1;      // 0..1
    int span  = blockIdx.x & 31;            // 32 spans of 128 groups
    int g     = threadIdx.x & 127;          // group lane
    int half  = threadIdx.x >> 7;           // 0..1 (channel half)
    int sp4   = span * 128 + g;

    const float4* base = reinterpret_cast<const float4*>(x)
                       + (size_t)b * C_ * HW4_
                       + (size_t)(chunk * CPC + half * CPT) * HW4_ + sp4;

    float4 sum = make_float4(0.f, 0.f, 0.f, 0.f);
    float4 mx  = make_float4(-INFINITY, -INFINITY, -INFINITY, -INFINITY);

    #pragma unroll 8
    for (int c = 0; c < CPT; ++c) {
        float4 v = __ldcs(base + c * HW4_);            // streaming, evict-first
        sum.x += v.x; sum.y += v.y; sum.z += v.z; sum.w += v.w;
        mx.x = fmaxf(mx.x, v.x); mx.y = fmaxf(mx.y, v.y);
        mx.z = fmaxf(mx.z, v.z); mx.w = fmaxf(mx.w, v.w);
    }

    if (half == 1) { s_sum[g] = sum; s_max[g] = mx; }
    __syncthreads();

    if (half == 0) {
        float4 s2 = s_sum[g], m2 = s_max[g];
        sum.x += s2.x; sum.y += s2.y; sum.z += s2.z; sum.w += s2.w;
        mx.x = fmaxf(mx.x, m2.x); mx.y = fmaxf(mx.y, m2.y);
        mx.z = fmaxf(mx.z, m2.z); mx.w = fmaxf(mx.w, m2.w);

        u64_t pol = mk_evict_last_policy();
        float4* p_sum = reinterpret_cast<float4*>(g_part)
                      + (size_t)chunk * B_ * 2 * HW4_ + (size_t)b * 2 * HW4_ + sp4;
        st_evict_last(p_sum,        sum, pol);
        st_evict_last(p_sum + HW4_, mx,  pol);
    }
}

// ---------------------------------------------------------------------------
// Kernel 2 (fused): combine 2 chunk partials -> mean/max tile in smem (vert +
// horiz halo, zero-padded), then 7x7 2-ch conv + sigmoid, 4-wide blocked.
// 1024 blocks x 256 threads; block = 8 rows x 32 cols of one batch.
// ---------------------------------------------------------------------------
__global__ __launch_bounds__(256) void fused_combine_conv_kernel(const float* __restrict__ wgt,
                                                                 float* __restrict__ out) {
    __shared__ float4 sm[2][TRR][GT];  // 4.4 KB
    __shared__ float  ws[98];

    if (threadIdx.x < 98) ws[threadIdx.x] = __ldg(wgt + threadIdx.x);

    int bid = blockIdx.x;
    int b   = bid >> 6;                // batch (64 tiles per batch)
    int rem = bid & 63;
    int ht  = rem >> 2;                // 0..15 (h tile)
    int wt  = rem & 3;                 // 0..3  (w tile)
    int h0  = ht * HT;                 // first output row
    int w0g = wt * 8;                  // first output float4 group
    int gb  = w0g - 1;                 // first halo group (may be -1)

    const size_t cs = (size_t)B_ * 2 * HW4_;   // chunk stride in float4
    const float inv = 1.0f / (float)C_;
    const float4* pb = reinterpret_cast<const float4*>(g_part) + (size_t)b * 2 * HW4_;

    // ---- Combine phase: 280 items; threads own i = tid and tid+256 ----
    {
        float4 regs[2][2];
        int    pl[2], rr[2], jj[2];
        bool   valid[2], own[2];

        #pragma unroll
        for (int k = 0; k < 2; ++k) {
            int i = threadIdx.x + k * 256;
            own[k] = (i < NIT);
            if (own[k]) {
                int plane = i / (TRR * GT);            // boundary at 140
                int r2    = i - plane * (TRR * GT);
                int r     = r2 / GT;
                int j     = r2 - r * GT;
                int hh    = h0 - 3 + r;
                int gg    = gb + j;
                pl[k] = plane; rr[k] = r; jj[k] = j;
                valid[k] = ((unsigned)hh < (unsigned)H_) && ((unsigned)gg < 32u);
                const float4* p = pb + (size_t)plane * HW4_
                                + (valid[k] ? (hh * 32 + gg) : 0);
                regs[k][0] = __ldg(p);
                regs[k][1] = __ldg(p + cs);
            }
        }

        #pragma unroll
        for (int k = 0; k < 2; ++k) {
            if (own[k]) {
                float4 v = make_float4(0.f, 0.f, 0.f, 0.f);
                if (valid[k]) {
                    if (pl[k] == 0) {
                        v.x = (regs[k][0].x + regs[k][1].x) * inv;
                        v.y = (regs[k][0].y + regs[k][1].y) * inv;
                        v.z = (regs[k][0].z + regs[k][1].z) * inv;
                        v.w = (regs[k][0].w + regs[k][1].w) * inv;
                    } else {
                        v.x = fmaxf(regs[k][0].x, regs[k][1].x);
                        v.y = fmaxf(regs[k][0].y, regs[k][1].y);
                        v.z = fmaxf(regs[k][0].z, regs[k][1].z);
                        v.w = fmaxf(regs[k][0].w, regs[k][1].w);
                    }
                }
                sm[pl[k]][rr[k]][jj[k]] = v;
            }
        }
    }
    __syncthreads();

    // ---- Conv phase: threads 0..63 -> (row r, output group j), 4 px each ----
    if (threadIdx.x < 64) {
        int r = threadIdx.x >> 3;          // 0..7
        int j = threadIdx.x & 7;           // 0..7

        float acc0 = 0.f, acc1 = 0.f, acc2 = 0.f, acc3 = 0.f;

        #pragma unroll
        for (int ch = 0; ch < 2; ++ch) {
            const float* wp = ws + ch * 49;
            #pragma unroll
            for (int kh = 0; kh < 7; ++kh) {
                float4 lo  = sm[ch][r + kh][j];        // halo (zero-padded)
                float4 mid = sm[ch][r + kh][j + 1];
                float4 hi  = sm[ch][r + kh][j + 2];
                float v[12] = { lo.x, lo.y, lo.z, lo.w,
                                mid.x, mid.y, mid.z, mid.w,
                                hi.x, hi.y, hi.z, hi.w };
                #pragma unroll
                for (int kw = 0; kw < 7; ++kw) {
                    float wv = wp[kh * 7 + kw];
                    acc0 = fmaf(v[kw + 1], wv, acc0);
                    acc1 = fmaf(v[kw + 2], wv, acc1);
                    acc2 = fmaf(v[kw + 3], wv, acc2);
                    acc3 = fmaf(v[kw + 4], wv, acc3);
                }
            }
        }

        float4 res;
        res.x = 1.0f / (1.0f + __expf(-acc0));
        res.y = 1.0f / (1.0f + __expf(-acc1));
        res.z = 1.0f / (1.0f + __expf(-acc2));
        res.w = 1.0f / (1.0f + __expf(-acc3));
        reinterpret_cast<float4*>(out)[(size_t)b * HW4_ + (h0 + r) * 32 + w0g + j] = res;
    }
}

extern "C" void kernel_launch(void* const* d_in, const int* in_sizes, int n_in,
                              void* d_out, int out_size) {
    const float* x = (const float*)d_in[0];
    const float* w = (const float*)d_in[1];
    float* out = (float*)d_out;

    reduce_partial_kernel<<<1024, 256>>>(x);            // 1024 blocks
    fused_combine_conv_kernel<<<1024, 256>>>(w, out);   // 1024 blocks
}